// round 17
// baseline (speedup 1.0000x reference)
#include <cuda_runtime.h>
#include <math.h>

#define CH 28
#define CP 32          // padded channel stride: 128B voxel rows
#define INV_SQ8 0.35355339059327373f
#define NMAX 1050000
#define SCHUNK 2048    // points per scatter block (256 thr x 8)
#define NBIN 4096      // 16 x 16 x 16 tiles of 8^3 voxels (z-major order)
#define TILE_ROWS (9 * 9 * 9)            // 729 voxel rows per staged tile
#define TILE_F4   (TILE_ROWS * 8)        // 5832 float4 = 93312 B smem

// Scratch (allocation-free contract: __device__ globals)
__device__ float  g_vol1[CH * 32 * 32 * 32];             //  3.5 MB
__device__ float  g_vol2[CH * 64 * 64 * 64];             //   28 MB
__device__ float  g_volF[(size_t)128 * 128 * 128 * CP];  //  268 MB (z,y,x,32)
__device__ float4 g_sorted[NMAX];                        // tile-sorted (x,y,z,idx)
__device__ int    g_hist[NBIN];
__device__ int    g_cursor[NBIN];

// ---------------------------------------------------------------------------
// 3D tile binning: bin = zt*256 + yt*16 + xt (z-major), tile = 8^3 voxels.
// ---------------------------------------------------------------------------
__device__ __forceinline__ int bin3(float x, float y, float z) {
    float px = (x / 1.5f + 1.0f) * 63.5f;
    float py = (y / 1.5f + 1.0f) * 63.5f;
    float pz = (z / 1.5f + 1.0f) * 63.5f;
    int x0 = min(max((int)floorf(px), 0), 126);
    int y0 = min(max((int)floorf(py), 0), 126);
    int z0 = min(max((int)floorf(pz), 0), 126);
    return ((z0 >> 3) << 8) | ((y0 >> 3) << 4) | (x0 >> 3);
}

__global__ void zero_hist_kernel() {      // 1024 threads
    int t = threadIdx.x;
#pragma unroll
    for (int i = 0; i < 4; i++) g_hist[t + i * 1024] = 0;
}

__global__ void hist_kernel(const float* __restrict__ xyz, int N) {
    __shared__ int sh[NBIN];
    for (int b = threadIdx.x; b < NBIN; b += blockDim.x) sh[b] = 0;
    __syncthreads();
    for (int i = blockIdx.x * blockDim.x + threadIdx.x; i < N;
         i += gridDim.x * blockDim.x)
        atomicAdd(&sh[bin3(xyz[3 * i], xyz[3 * i + 1], xyz[3 * i + 2])], 1);
    __syncthreads();
    for (int b = threadIdx.x; b < NBIN; b += blockDim.x)
        if (sh[b]) atomicAdd(&g_hist[b], sh[b]);
}

__global__ void scan_kernel() {           // 1024 threads, scans 4096
    __shared__ int ws[1024];
    int t = threadIdx.x;
    int4 v = ((const int4*)g_hist)[t];    // 4 consecutive bins
    int sum = v.x + v.y + v.z + v.w;
    ws[t] = sum;
    __syncthreads();
#pragma unroll
    for (int off = 1; off < 1024; off <<= 1) {
        int u = (t >= off) ? ws[t - off] : 0;
        __syncthreads();
        ws[t] += u;
        __syncthreads();
    }
    int base = ws[t] - sum;               // exclusive prefix of this group
    g_cursor[4 * t + 0] = base;
    g_cursor[4 * t + 1] = base + v.x;
    g_cursor[4 * t + 2] = base + v.x + v.y;
    g_cursor[4 * t + 3] = base + v.x + v.y + v.z;
}

// Block-aggregated scatter: local ranks via smem atomics, one global
// atomicAdd per (block, nonempty bin). After this, g_cursor = inclusive ends.
__global__ void scatter_kernel(const float* __restrict__ xyz, int N) {
    __shared__ int sh_count[NBIN];
    __shared__ int sh_base[NBIN];

    int tid = threadIdx.x;
    for (int b = tid; b < NBIN; b += 256) sh_count[b] = 0;
    __syncthreads();

    int start = blockIdx.x * SCHUNK;
    float px[8], py[8], pz[8];
    int code[8];                          // bin<<12 | local_rank

#pragma unroll
    for (int it = 0; it < 8; it++) {
        int i = start + it * 256 + tid;
        code[it] = -1;
        if (i < N) {
            px[it] = xyz[3 * i + 0];
            py[it] = xyz[3 * i + 1];
            pz[it] = xyz[3 * i + 2];
            int b = bin3(px[it], py[it], pz[it]);
            int r = atomicAdd(&sh_count[b], 1);
            code[it] = (b << 12) | r;
        }
    }
    __syncthreads();

    for (int b = tid; b < NBIN; b += 256) {
        int c = sh_count[b];
        sh_base[b] = c ? atomicAdd(&g_cursor[b], c) : 0;
    }
    __syncthreads();

#pragma unroll
    for (int it = 0; it < 8; it++) {
        if (code[it] >= 0) {
            int b = code[it] >> 12, r = code[it] & 0xFFF;
            int i = start + it * 256 + tid;
            g_sorted[sh_base[b] + r] =
                make_float4(px[it], py[it], pz[it], __int_as_float(i));
        }
    }
}

// ---------------------------------------------------------------------------
// Small IDWT levels, channel-major fp32 output.
// ---------------------------------------------------------------------------
template <int D>
__global__ void idwt_small(const float* __restrict__ approx,
                           const float* __restrict__ det,
                           float* __restrict__ out) {
    const int vol = CH * D * D * D;
    int idx = blockIdx.x * blockDim.x + threadIdx.x;
    if (idx >= vol) return;
    int k = idx % D;
    int j = (idx / D) % D;
    int i = (idx / (D * D)) % D;
    int c = idx / (D * D * D);

    float a[8];
    a[0] = approx[idx];
#pragma unroll
    for (int s = 1; s < 8; s++) a[s] = det[(size_t)(s - 1) * vol + idx];

    const int R = 2 * D;
    size_t base = (((size_t)c * R + 2 * i) * R + 2 * j) * R + 2 * k;
#pragma unroll
    for (int p = 0; p < 2; p++)
#pragma unroll
        for (int q = 0; q < 2; q++) {
            float b0 = 0.f, b1 = 0.f;
#pragma unroll
            for (int u = 0; u < 2; u++)
#pragma unroll
                for (int v = 0; v < 2; v++) {
                    float sgn = ((u & p) ^ (v & q)) ? -1.f : 1.f;
                    b0 += sgn * a[u * 4 + v * 2 + 0];
                    b1 += sgn * a[u * 4 + v * 2 + 1];
                }
            float2 val = make_float2(INV_SQ8 * (b0 + b1), INV_SQ8 * (b0 - b1));
            *(float2*)(out + base + ((size_t)p * R + q) * R) = val;
        }
}

// ---------------------------------------------------------------------------
// Final IDWT level (64 -> 128) fused with transpose to channel-last padded
// fp32 (z, y, x, 32). z DESCENDING so low-z planes are L2-hot at query start.
// ---------------------------------------------------------------------------
__global__ void idwt_final(const float* __restrict__ approx,
                           const float* __restrict__ det,
                           float* __restrict__ out) {
    const int D = 64, R = 128;
    const int vol = CH * D * D * D;
    int bid = blockIdx.x;
    int ktile = bid & 7;
    int j = (bid >> 3) & 63;
    int i = 63 - (bid >> 9);        // reverse z order
    int k0 = ktile * 8;

    int tid = threadIdx.x;
    int c  = tid >> 3;   // 0..31, only 0..27 active
    int kl = tid & 7;    // 0..7

    __shared__ __align__(16) float sh[4][16 * CH + 32];

    if (c < CH) {
        int idx = ((c * D + i) * D + j) * D + k0 + kl;
        float a[8];
        a[0] = __ldcs(approx + idx);
#pragma unroll
        for (int s = 1; s < 8; s++) a[s] = __ldcs(det + (size_t)(s - 1) * vol + idx);
#pragma unroll
        for (int p = 0; p < 2; p++)
#pragma unroll
            for (int q = 0; q < 2; q++) {
                float b0 = 0.f, b1 = 0.f;
#pragma unroll
                for (int u = 0; u < 2; u++)
#pragma unroll
                    for (int v = 0; v < 2; v++) {
                        float sgn = ((u & p) ^ (v & q)) ? -1.f : 1.f;
                        b0 += sgn * a[u * 4 + v * 2 + 0];
                        b1 += sgn * a[u * 4 + v * 2 + 1];
                    }
                sh[p * 2 + q][(2 * kl + 0) * CH + c] = INV_SQ8 * (b0 + b1);
                sh[p * 2 + q][(2 * kl + 1) * CH + c] = INV_SQ8 * (b0 - b1);
            }
    }
    __syncthreads();

    // 512 float4 stores: 4 octants x 16 x-values x 8 quads (f4==7 = zero pad).
#pragma unroll
    for (int t = tid; t < 512; t += 256) {
        int pq = t >> 7;
        int r  = t & 127;           // x*8 + f4
        int x  = r >> 3, f4 = r & 7;
        int p = pq >> 1, q = pq & 1;
        size_t base = (((size_t)(2 * i + p) * R + (2 * j + q)) * R + 2 * k0) * CP;
        float4 val = make_float4(0.f, 0.f, 0.f, 0.f);
        if (f4 < 7) {
            const float* src = &sh[pq][x * CH + 4 * f4];
            val = make_float4(src[0], src[1], src[2], src[3]);
        }
        ((float4*)(out + base))[r] = val;
    }
}

// ---------------------------------------------------------------------------
// Trilinear query: ONE BLOCK PER 3D TILE with EXPLICIT SMEM STAGING.
// Block loads its tile's 9x9x9 voxel rows (93 KB) with coalesced float4
// streams, then all ~250 points interpolate from smem. Global gather traffic
// drops from 1.02 GB (random 128B) to 381 MB (streamed).
// 512 threads, 2 blocks/SM (smem-limited) = 32 warps/SM.
// ---------------------------------------------------------------------------
__global__ __launch_bounds__(512)
void query_kernel(const float* __restrict__ vol, float* __restrict__ out) {
    extern __shared__ __align__(16) float4 s4[];   // TILE_F4 float4s

    int bin = blockIdx.x;
    int start = bin ? g_cursor[bin - 1] : 0;
    int end = g_cursor[bin];
    if (start >= end) return;

    int xt = bin & 15, yt = (bin >> 4) & 15, zt = bin >> 8;
    int tid = threadIdx.x;

    // ---- cooperative tile fill: 5832 float4s, coalesced 1152B row runs ----
    const float4* v4 = (const float4*)vol;
    for (int t = tid; t < TILE_F4; t += 512) {
        int row = t >> 3, f4 = t & 7;
        int lx = row % 9, rem = row / 9;
        int ly = rem % 9, lz = rem / 9;
        int gx = min(8 * xt + lx, 127);
        int gy = min(8 * yt + ly, 127);
        int gz = min(8 * zt + lz, 127);
        s4[t] = v4[(((size_t)gz * 128 + gy) * 128 + gx) * 8 + f4];
    }
    __syncthreads();

    // ---- interpolate from smem: 4 points per warp, float4 per lane ----
    int w = tid >> 5, lane = tid & 31;
    int sub = lane >> 3;            // 0..3
    int l = lane & 7;               // 0..7, active l<7

    for (int base_pt = start; base_pt < end; base_pt += 64) {
        int pt = base_pt + w * 4 + sub;
        if (pt >= end || l >= CH / 4) continue;

        float4 s = g_sorted[pt];
        int idx = __float_as_int(s.w);

        float px = (s.x / 1.5f + 1.0f) * 63.5f;
        float py = (s.y / 1.5f + 1.0f) * 63.5f;
        float pz = (s.z / 1.5f + 1.0f) * 63.5f;
        float flx = floorf(px), fly = floorf(py), flz = floorf(pz);
        float fx = px - flx, fy = py - fly, fz = pz - flz;
        int x0 = min(max((int)flx, 0), 126);
        int y0 = min(max((int)fly, 0), 126);
        int z0 = min(max((int)flz, 0), 126);

        int lx = x0 - 8 * xt, ly = y0 - 8 * yt, lz = z0 - 8 * zt;  // 0..7

        float wx1 = fx, wx0 = 1.f - fx;
        float wy1 = fy, wy0 = 1.f - fy;
        float wz1 = fz, wz0 = 1.f - fz;
        float w00 = wz0 * wy0, w01 = wz0 * wy1, w10 = wz1 * wy0, w11 = wz1 * wy1;

        const float4* b = s4 + ((lz * 9 + ly) * 9 + lx) * 8 + l;
        const int DX = 8, DY = 72, DZ = 648;

        float4 v000 = b[0];
        float4 v001 = b[DX];
        float4 v010 = b[DY];
        float4 v011 = b[DY + DX];
        float4 v100 = b[DZ];
        float4 v101 = b[DZ + DX];
        float4 v110 = b[DZ + DY];
        float4 v111 = b[DZ + DY + DX];

        float4 r;
        r.x = w00 * (wx0 * v000.x + wx1 * v001.x) + w01 * (wx0 * v010.x + wx1 * v011.x) +
              w10 * (wx0 * v100.x + wx1 * v101.x) + w11 * (wx0 * v110.x + wx1 * v111.x);
        r.y = w00 * (wx0 * v000.y + wx1 * v001.y) + w01 * (wx0 * v010.y + wx1 * v011.y) +
              w10 * (wx0 * v100.y + wx1 * v101.y) + w11 * (wx0 * v110.y + wx1 * v111.y);
        r.z = w00 * (wx0 * v000.z + wx1 * v001.z) + w01 * (wx0 * v010.z + wx1 * v011.z) +
              w10 * (wx0 * v100.z + wx1 * v101.z) + w11 * (wx0 * v110.z + wx1 * v111.z);
        r.w = w00 * (wx0 * v000.w + wx1 * v001.w) + w01 * (wx0 * v010.w + wx1 * v011.w) +
              w10 * (wx0 * v100.w + wx1 * v101.w) + w11 * (wx0 * v110.w + wx1 * v111.w);

        __stcs((float4*)(out + (size_t)idx * CH) + l, r);
    }
}

extern "C" void kernel_launch(void* const* d_in, const int* in_sizes, int n_in,
                              void* d_out, int out_size) {
    const float* approx = (const float*)d_in[0];   // (28,16,16,16)
    const float* det0   = (const float*)d_in[1];   // (7,28,16,16,16)
    const float* det1   = (const float*)d_in[2];   // (7,28,32,32,32)
    const float* det2   = (const float*)d_in[3];   // (7,28,64,64,64)
    const float* xyz    = (const float*)d_in[4];   // (N,3)
    int N = in_sizes[4] / 3;

    float *vol1, *vol2, *volF;
    cudaGetSymbolAddress((void**)&vol1, g_vol1);
    cudaGetSymbolAddress((void**)&vol2, g_vol2);
    cudaGetSymbolAddress((void**)&volF, g_volF);

    static int smem_set = 0;
    if (!smem_set) {
        cudaFuncSetAttribute(query_kernel,
                             cudaFuncAttributeMaxDynamicSharedMemorySize,
                             TILE_F4 * 16);
        smem_set = 1;
    }

    // 3D-tile sort chain
    zero_hist_kernel<<<1, 1024>>>();
    hist_kernel<<<448, 256>>>(xyz, N);
    scan_kernel<<<1, 1024>>>();
    scatter_kernel<<<(N + SCHUNK - 1) / SCHUNK, 256>>>(xyz, N);

    {   // level 0: 16 -> 32
        int n = CH * 16 * 16 * 16;
        idwt_small<16><<<(n + 255) / 256, 256>>>(approx, det0, vol1);
    }
    {   // level 1: 32 -> 64
        int n = CH * 32 * 32 * 32;
        idwt_small<32><<<(n + 255) / 256, 256>>>(vol1, det1, vol2);
    }
    // level 2: 64 -> 128, fused transpose to padded fp32 (z,y,x,32), z desc
    idwt_final<<<64 * 64 * 8, 256>>>(vol2, det2, volF);

    // trilinear gather: one block per tile, smem-staged
    query_kernel<<<NBIN, 512, TILE_F4 * 16>>>(volF, (float*)d_out);
}